// round 1
// baseline (speedup 1.0000x reference)
#include <cuda_runtime.h>
#include <cstdint>

typedef unsigned long long ull;

// ---------- packed f32x2 helpers (sm_103a) ----------
__device__ __forceinline__ ull pack2(float a, float b) {
    ull r; asm("mov.b64 %0, {%1, %2};" : "=l"(r) : "f"(a), "f"(b)); return r;
}
__device__ __forceinline__ void unpack2(ull v, float& a, float& b) {
    asm("mov.b64 {%0, %1}, %2;" : "=f"(a), "=f"(b) : "l"(v));
}
__device__ __forceinline__ ull ffma2(ull a, ull b, ull c) {
    ull d; asm("fma.rn.f32x2 %0, %1, %2, %3;" : "=l"(d) : "l"(a), "l"(b), "l"(c)); return d;
}
__device__ __forceinline__ ull relu2(ull v) {
    float a, b; unpack2(v, a, b);
    return pack2(fmaxf(a, 0.f), fmaxf(b, 0.f));
}

#define NJ 24
#define JW 104   // ull entries per joint: 13 rows x 8 (7 dup weights + dup bias)

// second layer (6 outputs from h[7]) shared by root and normal joints
__device__ __forceinline__ void layer2(const ull* wp, const ull* h, ull* fo,
                                       float* fa, float* fb) {
#pragma unroll
    for (int o = 0; o < 6; ++o) {
        const ulonglong2* r = reinterpret_cast<const ulonglong2*>(wp + 56 + o * 8);
        ulonglong2 q0 = r[0], q1 = r[1], q2 = r[2], q3 = r[3];
        ull acc = ffma2(q0.x, h[0], q3.y);
        acc = ffma2(q0.y, h[1], acc);
        acc = ffma2(q1.x, h[2], acc);
        acc = ffma2(q1.y, h[3], acc);
        acc = ffma2(q2.x, h[4], acc);
        acc = ffma2(q2.y, h[5], acc);
        acc = ffma2(q3.x, h[6], acc);
        float a, b; unpack2(acc, a, b);
        a = fmaxf(a, 0.f); b = fmaxf(b, 0.f);
        fa[o] = a; fb[o] = b;
        fo[o] = pack2(a, b);
    }
}

__device__ __forceinline__ void joint_fwd(const ull* wp, ull xp,
                                          const ull* pf, ull* fo,
                                          float* fa, float* fb) {
    ull h[7];
#pragma unroll
    for (int o = 0; o < 7; ++o) {
        const ulonglong2* r = reinterpret_cast<const ulonglong2*>(wp + o * 8);
        ulonglong2 q0 = r[0], q1 = r[1], q2 = r[2], q3 = r[3];
        ull acc = ffma2(q0.x, xp, q3.y);      // w0 * x + bias
        acc = ffma2(q0.y, pf[0], acc);
        acc = ffma2(q1.x, pf[1], acc);
        acc = ffma2(q1.y, pf[2], acc);
        acc = ffma2(q2.x, pf[3], acc);
        acc = ffma2(q2.y, pf[4], acc);
        acc = ffma2(q3.x, pf[5], acc);
        h[o] = relu2(acc);
    }
    layer2(wp, h, fo, fa, fb);
}

// root joint: parent features are zero -> h_o = relu(w0*x + b)
__device__ __forceinline__ void root_fwd(const ull* wp, ull xp, ull* fo,
                                         float* fa, float* fb) {
    ull h[7];
#pragma unroll
    for (int o = 0; o < 7; ++o) {
        ull w0 = wp[o * 8];
        ull bb = wp[o * 8 + 7];
        h[o] = relu2(ffma2(w0, xp, bb));
    }
    layer2(wp, h, fo, fa, fb);
}

__global__ void __launch_bounds__(128)
StructureEncoder1D_kernel(const float* __restrict__ x,
                          const float* __restrict__ W1,
                          const float* __restrict__ b1,
                          const float* __restrict__ W2,
                          const float* __restrict__ b2,
                          float* __restrict__ out, int B) {
    __shared__ __align__(16) ull sw[NJ * JW];

    // cooperative fill: each ull = one weight duplicated into both fp32 halves
    for (int i = threadIdx.x; i < NJ * JW; i += blockDim.x) {
        int j = i / JW, r = i % JW, row = r >> 3, c = r & 7;
        float v;
        if (row < 7) {
            v = (c < 7) ? W1[j * 49 + row * 7 + c] : b1[j * 7 + row];
        } else {
            int rr = row - 7;
            v = (c < 7) ? W2[j * 42 + rr * 7 + c] : b2[j * 6 + rr];
        }
        ull u = (ull)__float_as_uint(v);
        sw[i] = u | (u << 32);
    }
    __syncthreads();

    int g  = blockIdx.x * blockDim.x + threadIdx.x;
    int e0 = ((g >> 5) << 6) | (g & 31);   // warp covers 64 consecutive elements
    int e1 = e0 + 32;
    bool p0 = e0 < B;
    bool p1 = e1 < B;
    if (!p0) return;

    // load x rows (24 floats each, 16B aligned since 24*4 = 96)
    float xa[24], xb[24];
    {
        const float4* q = reinterpret_cast<const float4*>(x + (size_t)e0 * 24);
#pragma unroll
        for (int i = 0; i < 6; ++i) {
            float4 v = q[i];
            xa[4 * i] = v.x; xa[4 * i + 1] = v.y; xa[4 * i + 2] = v.z; xa[4 * i + 3] = v.w;
        }
    }
    if (p1) {
        const float4* q = reinterpret_cast<const float4*>(x + (size_t)e1 * 24);
#pragma unroll
        for (int i = 0; i < 6; ++i) {
            float4 v = q[i];
            xb[4 * i] = v.x; xb[4 * i + 1] = v.y; xb[4 * i + 2] = v.z; xb[4 * i + 3] = v.w;
        }
    } else {
#pragma unroll
        for (int i = 0; i < 24; ++i) xb[i] = 0.f;
    }

    float* o0 = out + (size_t)e0 * 144;
    float* o1 = out + (size_t)e1 * 144;

    ull f0[6], f9[6], cur[6];
    float fa[6], fb[6];

#define XP(J) pack2(xa[J], xb[J])
#define ST(J) do {                                                          \
        ((float2*)(o0 + (J) * 6))[0] = make_float2(fa[0], fa[1]);           \
        ((float2*)(o0 + (J) * 6))[1] = make_float2(fa[2], fa[3]);           \
        ((float2*)(o0 + (J) * 6))[2] = make_float2(fa[4], fa[5]);           \
        if (p1) {                                                           \
            ((float2*)(o1 + (J) * 6))[0] = make_float2(fb[0], fb[1]);       \
            ((float2*)(o1 + (J) * 6))[1] = make_float2(fb[2], fb[3]);       \
            ((float2*)(o1 + (J) * 6))[2] = make_float2(fb[4], fb[5]);       \
        }                                                                   \
    } while (0)

    // DFS over the tree; live packed features: cur, f0 (joint 0), f9 (joint 9)
    root_fwd (sw +  0 * JW, XP(0),        f0,  fa, fb); ST(0);
    joint_fwd(sw +  1 * JW, XP(1),  f0,  cur,  fa, fb); ST(1);
    joint_fwd(sw +  4 * JW, XP(4),  cur, cur,  fa, fb); ST(4);
    joint_fwd(sw +  7 * JW, XP(7),  cur, cur,  fa, fb); ST(7);
    joint_fwd(sw + 10 * JW, XP(10), cur, cur,  fa, fb); ST(10);
    joint_fwd(sw +  2 * JW, XP(2),  f0,  cur,  fa, fb); ST(2);
    joint_fwd(sw +  5 * JW, XP(5),  cur, cur,  fa, fb); ST(5);
    joint_fwd(sw +  8 * JW, XP(8),  cur, cur,  fa, fb); ST(8);
    joint_fwd(sw + 11 * JW, XP(11), cur, cur,  fa, fb); ST(11);
    joint_fwd(sw +  3 * JW, XP(3),  f0,  cur,  fa, fb); ST(3);
    joint_fwd(sw +  6 * JW, XP(6),  cur, cur,  fa, fb); ST(6);
    joint_fwd(sw +  9 * JW, XP(9),  cur, f9,   fa, fb); ST(9);
    joint_fwd(sw + 12 * JW, XP(12), f9,  cur,  fa, fb); ST(12);
    joint_fwd(sw + 15 * JW, XP(15), cur, cur,  fa, fb); ST(15);
    joint_fwd(sw + 13 * JW, XP(13), f9,  cur,  fa, fb); ST(13);
    joint_fwd(sw + 16 * JW, XP(16), cur, cur,  fa, fb); ST(16);
    joint_fwd(sw + 18 * JW, XP(18), cur, cur,  fa, fb); ST(18);
    joint_fwd(sw + 20 * JW, XP(20), cur, cur,  fa, fb); ST(20);
    joint_fwd(sw + 22 * JW, XP(22), cur, cur,  fa, fb); ST(22);
    joint_fwd(sw + 14 * JW, XP(14), f9,  cur,  fa, fb); ST(14);
    joint_fwd(sw + 17 * JW, XP(17), cur, cur,  fa, fb); ST(17);
    joint_fwd(sw + 19 * JW, XP(19), cur, cur,  fa, fb); ST(19);
    joint_fwd(sw + 21 * JW, XP(21), cur, cur,  fa, fb); ST(21);
    joint_fwd(sw + 23 * JW, XP(23), cur, cur,  fa, fb); ST(23);

#undef XP
#undef ST
}

extern "C" void kernel_launch(void* const* d_in, const int* in_sizes, int n_in,
                              void* d_out, int out_size) {
    const float* x  = (const float*)d_in[0];
    const float* W1 = (const float*)d_in[1];
    const float* b1 = (const float*)d_in[2];
    const float* W2 = (const float*)d_in[3];
    const float* b2 = (const float*)d_in[4];
    float* out = (float*)d_out;

    int B = in_sizes[0] / 24;
    int warps  = (B + 63) / 64;          // each warp covers 64 elements
    int blocks = (warps + 3) / 4;        // 128 threads = 4 warps per block
    StructureEncoder1D_kernel<<<blocks, 128>>>(x, W1, b1, W2, b2, out, B);
}

// round 4
// speedup vs baseline: 2.5657x; 2.5657x over previous
#include <cuda_runtime.h>
#include <cstdint>

typedef unsigned long long ull;

// ---------- packed f32x2 helpers (sm_103a) ----------
__device__ __forceinline__ ull pack2(float a, float b) {
    ull r; asm("mov.b64 %0, {%1, %2};" : "=l"(r) : "f"(a), "f"(b)); return r;
}
__device__ __forceinline__ void unpack2(ull v, float& a, float& b) {
    asm("mov.b64 {%0, %1}, %2;" : "=f"(a), "=f"(b) : "l"(v));
}
__device__ __forceinline__ ull ffma2(ull a, ull b, ull c) {
    ull d; asm("fma.rn.f32x2 %0, %1, %2, %3;" : "=l"(d) : "l"(a), "l"(b), "l"(c)); return d;
}
__device__ __forceinline__ ull relu2(ull v) {
    float a, b; unpack2(v, a, b);
    return pack2(fmaxf(a, 0.f), fmaxf(b, 0.f));
}

#define NJ 24
#define JW 104          // ull per joint: 13 rows x 8 (7 dup weights + dup bias)
#define WPB 8           // warps per block
#define TPAD 74         // tile row stride in floats (EVEN -> aligned STS.64; 74=2*37, conflict-free phases)
#define TILE_FLOATS (64 * TPAD)
#define SW_BYTES (NJ * JW * 8)                         // 19968
#define SMEM_BYTES (SW_BYTES + WPB * TILE_FLOATS * 4)  // 171520

// ---- layer 2: 6 outputs from h[7]; results to fa/fb + packed fo ----
__device__ __forceinline__ void layer2(const ull* wp, const ull* h, ull* fo,
                                       float* fa, float* fb) {
#pragma unroll
    for (int o = 0; o < 6; ++o) {
        const ulonglong2* r = reinterpret_cast<const ulonglong2*>(wp + 56 + o * 8);
        ulonglong2 q0 = r[0], q1 = r[1], q2 = r[2], q3 = r[3];
        ull acc = ffma2(q0.x, h[0], q3.y);
        acc = ffma2(q0.y, h[1], acc);
        acc = ffma2(q1.x, h[2], acc);
        acc = ffma2(q1.y, h[3], acc);
        acc = ffma2(q2.x, h[4], acc);
        acc = ffma2(q2.y, h[5], acc);
        acc = ffma2(q3.x, h[6], acc);
        float a, b; unpack2(acc, a, b);
        a = fmaxf(a, 0.f); b = fmaxf(b, 0.f);
        fa[o] = a; fb[o] = b;
        fo[o] = pack2(a, b);
    }
}

__device__ __forceinline__ void joint_fwd(const ull* wp, ull xp,
                                          const ull* pf, ull* fo,
                                          float* fa, float* fb) {
    ull h[7];
#pragma unroll
    for (int o = 0; o < 7; ++o) {
        const ulonglong2* r = reinterpret_cast<const ulonglong2*>(wp + o * 8);
        ulonglong2 q0 = r[0], q1 = r[1], q2 = r[2], q3 = r[3];
        ull acc = ffma2(q0.x, xp, q3.y);      // w0 * x + bias
        acc = ffma2(q0.y, pf[0], acc);
        acc = ffma2(q1.x, pf[1], acc);
        acc = ffma2(q1.y, pf[2], acc);
        acc = ffma2(q2.x, pf[3], acc);
        acc = ffma2(q2.y, pf[4], acc);
        acc = ffma2(q3.x, pf[5], acc);
        h[o] = relu2(acc);
    }
    layer2(wp, h, fo, fa, fb);
}

__device__ __forceinline__ void root_fwd(const ull* wp, ull xp, ull* fo,
                                         float* fa, float* fb) {
    ull h[7];
#pragma unroll
    for (int o = 0; o < 7; ++o) {
        ull w0 = wp[o * 8];
        ull bb = wp[o * 8 + 7];
        h[o] = relu2(ffma2(w0, xp, bb));
    }
    layer2(wp, h, fo, fa, fb);
}

__global__ void __launch_bounds__(WPB * 32)
StructureEncoder1D_kernel(const float* __restrict__ x,
                          const float* __restrict__ W1,
                          const float* __restrict__ b1,
                          const float* __restrict__ W2,
                          const float* __restrict__ b2,
                          float* __restrict__ out, int B) {
    extern __shared__ __align__(16) char dynsmem[];
    ull*   sw    = reinterpret_cast<ull*>(dynsmem);
    float* tiles = reinterpret_cast<float*>(dynsmem + SW_BYTES);

    // ---- cooperative weight fill: each ull = one weight duplicated ----
    for (int i = threadIdx.x; i < NJ * JW; i += blockDim.x) {
        int j = i / JW, r = i % JW, row = r >> 3, c = r & 7;
        float v;
        if (row < 7) {
            v = (c < 7) ? W1[j * 49 + row * 7 + c] : b1[j * 7 + row];
        } else {
            int rr = row - 7;
            v = (c < 7) ? W2[j * 42 + rr * 7 + c] : b2[j * 6 + rr];
        }
        ull u = (ull)__float_as_uint(v);
        sw[i] = u | (u << 32);
    }
    __syncthreads();

    const int lane   = threadIdx.x & 31;
    const int warpId = threadIdx.x >> 5;
    const int warpBase = (blockIdx.x * WPB + warpId) * 64;   // first element of warp
    if (warpBase >= B) return;

    float* tile = tiles + warpId * TILE_FLOATS;

    // ---- stage x: coalesced LDG.128 -> padded smem (row stride 25 floats) ----
    {
        const float4* xin = reinterpret_cast<const float4*>(x);
#pragma unroll
        for (int k = 0; k < 12; ++k) {
            int i = k * 32 + lane;               // i in [0,384): 64 rows x 6 float4
            int r = i / 6, c = i % 6;
            float4 v = make_float4(0.f, 0.f, 0.f, 0.f);
            if (warpBase + r < B) v = xin[(size_t)(warpBase + r) * 6 + c];
            float* d = tile + r * 25 + c * 4;
            d[0] = v.x; d[1] = v.y; d[2] = v.z; d[3] = v.w;
        }
    }
    __syncwarp();

    // ---- read x rows (lane, lane+32) from smem, pack into registers ----
    ull xp[24];
    {
        const float* ra = tile + lane * 25;
        const float* rb = tile + (lane + 32) * 25;
#pragma unroll
        for (int j = 0; j < 24; ++j) xp[j] = pack2(ra[j], rb[j]);
    }
    __syncwarp();

    float* ta = tile + lane * TPAD;          // row for element e0 (even float offset)
    float* tb = tile + (lane + 32) * TPAD;   // row for element e1

    ull f0[6], f9[6], cur[6];
    float fa[6], fb[6];

#define ST(CB) do {                                                    \
        ((float2*)(ta + (CB)))[0] = make_float2(fa[0], fa[1]);         \
        ((float2*)(ta + (CB)))[1] = make_float2(fa[2], fa[3]);         \
        ((float2*)(ta + (CB)))[2] = make_float2(fa[4], fa[5]);         \
        ((float2*)(tb + (CB)))[0] = make_float2(fb[0], fb[1]);         \
        ((float2*)(tb + (CB)))[1] = make_float2(fb[2], fb[3]);         \
        ((float2*)(tb + (CB)))[2] = make_float2(fb[4], fb[5]);         \
    } while (0)

#define FLUSH(H) do {                                                          \
        __syncwarp();                                                          \
        _Pragma("unroll")                                                      \
        for (int k = 0; k < 36; ++k) {                                         \
            int i = k * 32 + lane;               /* [0,1152): 64 rows x 18 */  \
            int r = i / 18, c = i % 18;                                        \
            if (warpBase + r < B) {                                            \
                const float2* s = reinterpret_cast<const float2*>(             \
                    tile + r * TPAD + c * 4);                                  \
                float2 lo = s[0], hi = s[1];                                   \
                *reinterpret_cast<float4*>(                                    \
                    out + (size_t)(warpBase + r) * 144 + (H) * 72 + c * 4) =   \
                    make_float4(lo.x, lo.y, hi.x, hi.y);                       \
            }                                                                  \
        }                                                                      \
        __syncwarp();                                                          \
    } while (0)

    // ---- first half: DFS over joints 0..11 (cols = j*6) ----
    root_fwd (sw +  0 * JW, xp[0],        f0,  fa, fb); ST(0 * 6);
    joint_fwd(sw +  1 * JW, xp[1],  f0,  cur,  fa, fb); ST(1 * 6);
    joint_fwd(sw +  4 * JW, xp[4],  cur, cur,  fa, fb); ST(4 * 6);
    joint_fwd(sw +  7 * JW, xp[7],  cur, cur,  fa, fb); ST(7 * 6);
    joint_fwd(sw + 10 * JW, xp[10], cur, cur,  fa, fb); ST(10 * 6);
    joint_fwd(sw +  2 * JW, xp[2],  f0,  cur,  fa, fb); ST(2 * 6);
    joint_fwd(sw +  5 * JW, xp[5],  cur, cur,  fa, fb); ST(5 * 6);
    joint_fwd(sw +  8 * JW, xp[8],  cur, cur,  fa, fb); ST(8 * 6);
    joint_fwd(sw + 11 * JW, xp[11], cur, cur,  fa, fb); ST(11 * 6);
    joint_fwd(sw +  3 * JW, xp[3],  f0,  cur,  fa, fb); ST(3 * 6);
    joint_fwd(sw +  6 * JW, xp[6],  cur, cur,  fa, fb); ST(6 * 6);
    joint_fwd(sw +  9 * JW, xp[9],  cur, f9,   fa, fb); ST(9 * 6);

    FLUSH(0);

    // ---- second half: joints 12..23 (cols = (j-12)*6) ----
    joint_fwd(sw + 12 * JW, xp[12], f9,  cur,  fa, fb); ST(0 * 6);
    joint_fwd(sw + 15 * JW, xp[15], cur, cur,  fa, fb); ST(3 * 6);
    joint_fwd(sw + 13 * JW, xp[13], f9,  cur,  fa, fb); ST(1 * 6);
    joint_fwd(sw + 16 * JW, xp[16], cur, cur,  fa, fb); ST(4 * 6);
    joint_fwd(sw + 18 * JW, xp[18], cur, cur,  fa, fb); ST(6 * 6);
    joint_fwd(sw + 20 * JW, xp[20], cur, cur,  fa, fb); ST(8 * 6);
    joint_fwd(sw + 22 * JW, xp[22], cur, cur,  fa, fb); ST(10 * 6);
    joint_fwd(sw + 14 * JW, xp[14], f9,  cur,  fa, fb); ST(2 * 6);
    joint_fwd(sw + 17 * JW, xp[17], cur, cur,  fa, fb); ST(5 * 6);
    joint_fwd(sw + 19 * JW, xp[19], cur, cur,  fa, fb); ST(7 * 6);
    joint_fwd(sw + 21 * JW, xp[21], cur, cur,  fa, fb); ST(9 * 6);
    joint_fwd(sw + 23 * JW, xp[23], cur, cur,  fa, fb); ST(11 * 6);

    FLUSH(1);

#undef ST
#undef FLUSH
}

extern "C" void kernel_launch(void* const* d_in, const int* in_sizes, int n_in,
                              void* d_out, int out_size) {
    const float* x  = (const float*)d_in[0];
    const float* W1 = (const float*)d_in[1];
    const float* b1 = (const float*)d_in[2];
    const float* W2 = (const float*)d_in[3];
    const float* b2 = (const float*)d_in[4];
    float* out = (float*)d_out;

    int B = in_sizes[0] / 24;
    int warps  = (B + 63) / 64;
    int blocks = (warps + WPB - 1) / WPB;

    cudaFuncSetAttribute(StructureEncoder1D_kernel,
                         cudaFuncAttributeMaxDynamicSharedMemorySize, SMEM_BYTES);
    StructureEncoder1D_kernel<<<blocks, WPB * 32, SMEM_BYTES>>>(x, W1, b1, W2, b2, out, B);
}